// round 12
// baseline (speedup 1.0000x reference)
#include <cuda_runtime.h>
#include <cstdint>

// ---------------------------------------------------------------------------
// R10 structure (memset node + atomic kernel — measured winner), leaner:
//   * 2 batches per warp -> grid = B/2 x 32 (halves blocks + REDGs).
//   * 16 lanes per batch scan 64 labels via int4; both 6-bit presence masks
//     packed in one u32 (bits 0-5 / 16-21), ONE redux.or.
//     Presence-OR is monotone => early exit exact. p(miss after 64 uniform
//     labels) ~ 5e-5 per batch; cold loop finishes the scan (correct on any
//     data, just slower).
//   * BCE log terms (torch clamp at -100) for the 12 (batch,class) entries
//     are computed and PRE-SCALED by 1/n_terms while the target load is in
//     flight -> no FDIV after the mask resolves.
//   * Tail: select -> 4 shfl -> one return-less atomicAdd (REDG) to out[0],
//     which a cudaMemsetAsync node zeroed.
// ---------------------------------------------------------------------------
__global__ void __launch_bounds__(32, 32)
se_loss_pair_kernel(const int* __restrict__ target,
                    const float* __restrict__ se_pred,
                    float* __restrict__ out,
                    int n_vec4_per_batch, int n_batches, int n_terms,
                    float inv_n_terms) {
    const int lane    = threadIdx.x;
    const int half    = lane >> 4;          // which batch of the pair (scan)
    const int sublane = lane & 15;
    const int b_scan  = (blockIdx.x << 1) + half;
    const bool scan_valid = (b_scan < n_batches);

    // --- issue the target load first (longest latency) ---
    const int4* __restrict__ t4 = reinterpret_cast<const int4*>(target)
                                  + (long long)b_scan * n_vec4_per_batch;
    int4 v0 = make_int4(0, 0, 0, 0);
    const bool ld0 = scan_valid && (sublane < n_vec4_per_batch);
    if (ld0) v0 = t4[sublane];

    // --- overlap: pre-scaled BCE log terms (lanes 0..11) ---
    // lane -> (batch = 2*blockIdx.x + lane/6, class = lane%6)
    const int term_idx = blockIdx.x * 12 + lane;
    const bool term_valid = (lane < 12) && (term_idx < n_terms);
    float v_present = 0.0f, v_absent = 0.0f;
    int t_shift = 0;
    if (term_valid) {
        const float p = se_pred[term_idx];
        v_present = -fmaxf(logf(p),    -100.0f) * inv_n_terms;  // t = 1
        v_absent  = -fmaxf(log1pf(-p), -100.0f) * inv_n_terms;  // t = 0
        const int bhalf = (lane >= 6);
        t_shift = (bhalf << 4) + (lane - bhalf * 6);   // bit in packed mask
    }

    // --- packed presence masks ---
    const unsigned DONE  = 0x003F003Fu;
    const int      shamt = half << 4;
    unsigned acc = scan_valid ? 0u : (0x3Fu << shamt);  // missing batch = done
    if (ld0) {
        unsigned bits = (1u << (v0.x & 31)) | (1u << (v0.y & 31)) |
                        (1u << (v0.z & 31)) | (1u << (v0.w & 31));
        acc |= (bits & 0x3Fu) << shamt;
    }
    acc = __reduce_or_sync(0xffffffffu, acc);

    if ((acc & DONE) != DONE) {                 // cold path: finish the scan
        const int max_iter = (n_vec4_per_batch + 15) >> 4;
        for (int it = 1; it < max_iter; it++) {
            int idx = (it << 4) + sublane;
            unsigned a = 0u;
            if (scan_valid && idx < n_vec4_per_batch) {
                int4 v = t4[idx];
                unsigned bits = (1u << (v.x & 31)) | (1u << (v.y & 31)) |
                                (1u << (v.z & 31)) | (1u << (v.w & 31));
                a = (bits & 0x3Fu) << shamt;
            }
            acc |= __reduce_or_sync(0xffffffffu, a);
            if ((acc & DONE) == DONE) break;
        }
    }

    // --- select + reduce 12 pre-scaled terms (lanes 12..31 carry 0) ---
    float v = 0.0f;
    if (term_valid)
        v = ((acc >> t_shift) & 1u) ? v_present : v_absent;
    #pragma unroll
    for (int o = 8; o > 0; o >>= 1) v += __shfl_down_sync(0xffffffffu, v, o);

    if (lane == 0) atomicAdd(out, v);           // return unused -> REDG
}

// ---------------------------------------------------------------------------
extern "C" void kernel_launch(void* const* d_in, const int* in_sizes, int n_in,
                              void* d_out, int out_size) {
    // Resolve inputs by size: se_pred has 64*6 = 384 elements; target is huge.
    int se_idx = 0, tg_idx = 1;
    if (n_in >= 2 && in_sizes[0] > in_sizes[1]) { se_idx = 1; tg_idx = 0; }

    const float* se_pred = (const float*)d_in[se_idx];
    const int*   target  = (const int*)d_in[tg_idx];
    float* out = (float*)d_out;

    const int n_terms   = in_sizes[se_idx];        // 384
    const int B         = n_terms / 6;             // 64
    const int per_batch = in_sizes[tg_idx] / B;    // 262144 int32 labels
    const int n_vec4    = per_batch / 4;           // int4 count per batch
    const int n_pairs   = (B + 1) >> 1;            // 32 blocks
    const float inv_n   = 1.0f / (float)n_terms;

    cudaMemsetAsync(out, 0, sizeof(float), 0);     // zero the accumulator
    se_loss_pair_kernel<<<n_pairs, 32>>>(target, se_pred, out,
                                         n_vec4, B, n_terms, inv_n);
}

// round 13
// speedup vs baseline: 1.1921x; 1.1921x over previous
#include <cuda_runtime.h>
#include <cstdint>

// ---------------------------------------------------------------------------
// Best-measured structure (R10: memset node + return-less atomic kernel),
// with R12's FDIV elimination folded in. Reproducibility probe for the
// 6.24 us e2e measurement.
//
// One warp per batch (grid = B x 32):
//   1. Issue the 128-label target load (32 lanes x int4) FIRST.
//   2. While in flight: lanes 0..5 load se_pred and compute BOTH clamped BCE
//      log terms (torch BCELoss: log clamped at -100), PRE-SCALED by
//      1/n_terms so no FDIV/FMUL remains after the mask resolves.
//   3. One redux.or -> 6-bit presence mask. Presence-OR is monotone, so early
//      exit is exact: p(miss after 128 uniform labels) ~ 4e-10; adversarial
//      data degrades to a full (still correct) scan via the cold loop.
//   4. Select present/absent, 3 shfl, one return-less atomicAdd (REDG) into
//      out[0] (zeroed by the cudaMemsetAsync node). No fences, no counters.
// ---------------------------------------------------------------------------
__global__ void __launch_bounds__(32, 32)
se_loss_kernel(const int* __restrict__ target,
               const float* __restrict__ se_pred,
               float* __restrict__ out,
               int n_vec4_per_batch, int n_terms, float inv_n_terms) {
    const int lane = threadIdx.x;
    const int b    = blockIdx.x;

    // --- issue the target load first (longest latency) ---
    const int4* __restrict__ t4 = reinterpret_cast<const int4*>(target)
                                  + (long long)b * n_vec4_per_batch;
    int4 v0 = make_int4(0, 0, 0, 0);
    const bool ld0 = (lane < n_vec4_per_batch);
    if (ld0) v0 = t4[lane];

    // --- overlap: pre-scaled BCE log terms (lanes 0..5) ---
    const int term_idx = b * 6 + lane;
    const bool term_valid = (lane < 6) && (term_idx < n_terms);
    float v_present = 0.0f, v_absent = 0.0f;
    if (term_valid) {
        const float p = se_pred[term_idx];
        v_present = -fmaxf(logf(p),    -100.0f) * inv_n_terms;  // t = 1
        v_absent  = -fmaxf(log1pf(-p), -100.0f) * inv_n_terms;  // t = 0
    }

    // --- presence mask ---
    unsigned acc = 0u;
    if (ld0) {
        acc = (1u << (v0.x & 31)) | (1u << (v0.y & 31)) |
              (1u << (v0.z & 31)) | (1u << (v0.w & 31));
    }
    acc = __reduce_or_sync(0xffffffffu, acc) & 0x3Fu;

    if (acc != 0x3Fu) {                          // cold path: finish the scan
        for (int base = 32; base < n_vec4_per_batch; base += 32) {
            int idx = base + lane;
            unsigned a = 0u;
            if (idx < n_vec4_per_batch) {
                int4 v = t4[idx];
                a = (1u << (v.x & 31)) | (1u << (v.y & 31)) |
                    (1u << (v.z & 31)) | (1u << (v.w & 31));
            }
            acc |= __reduce_or_sync(0xffffffffu, a) & 0x3Fu;
            if (acc == 0x3Fu) break;
        }
    }

    // --- select + reduce this batch's 6 pre-scaled terms ---
    float v = 0.0f;
    if (term_valid)
        v = ((acc >> lane) & 1u) ? v_present : v_absent;
    #pragma unroll
    for (int o = 4; o > 0; o >>= 1) v += __shfl_down_sync(0xffffffffu, v, o);

    if (lane == 0) atomicAdd(out, v);            // return unused -> REDG
}

// ---------------------------------------------------------------------------
extern "C" void kernel_launch(void* const* d_in, const int* in_sizes, int n_in,
                              void* d_out, int out_size) {
    // Resolve inputs by size: se_pred has 64*6 = 384 elements; target is huge.
    int se_idx = 0, tg_idx = 1;
    if (n_in >= 2 && in_sizes[0] > in_sizes[1]) { se_idx = 1; tg_idx = 0; }

    const float* se_pred = (const float*)d_in[se_idx];
    const int*   target  = (const int*)d_in[tg_idx];
    float* out = (float*)d_out;

    const int n_terms   = in_sizes[se_idx];        // 384
    const int B         = n_terms / 6;             // 64
    const int per_batch = in_sizes[tg_idx] / B;    // 262144 int32 labels
    const int n_vec4    = per_batch / 4;           // int4 count per batch
    const float inv_n   = 1.0f / (float)n_terms;

    cudaMemsetAsync(out, 0, sizeof(float), 0);     // zero the accumulator
    se_loss_kernel<<<B, 32>>>(target, se_pred, out, n_vec4, n_terms, inv_n);
}

// round 14
// speedup vs baseline: 1.2410x; 1.0410x over previous
#include <cuda_runtime.h>
#include <cstdint>

// ---------------------------------------------------------------------------
// Best-measured family (memset node + return-less atomic kernel), repackaged:
// 4 independent warps per block -> grid = B/4 x 128 (16 CTAs instead of 64,
// less dispatch). No smem, no barriers: each warp owns one batch end-to-end
// and issues its own REDG.
//
// Per-warp hot path (unchanged from the proven R10/R13 kernel):
//   1. Issue the 128-label target load (32 lanes x int4) FIRST.
//   2. While in flight: lanes 0..5 load se_pred and compute BOTH clamped BCE
//      log terms (torch BCELoss: log clamped at -100), PRE-SCALED by
//      1/n_terms (no FDIV after the mask resolves).
//   3. One redux.or -> 6-bit presence mask. Presence-OR is monotone, so the
//      early exit is exact: p(miss after 128 uniform labels) ~ 4e-10;
//      adversarial data degrades to a full (still correct) scan.
//   4. Select present/absent, 3 shfl, one return-less atomicAdd (REDG) into
//      out[0], zeroed by the cudaMemsetAsync node.
// ---------------------------------------------------------------------------
__global__ void __launch_bounds__(128, 8)
se_loss_kernel(const int* __restrict__ target,
               const float* __restrict__ se_pred,
               float* __restrict__ out,
               int n_vec4_per_batch, int n_batches, int n_terms,
               float inv_n_terms) {
    const int lane = threadIdx.x & 31;
    const int wid  = threadIdx.x >> 5;
    const int b    = (blockIdx.x << 2) + wid;      // batch owned by this warp
    if (b >= n_batches) return;                    // whole-warp uniform exit

    // --- issue the target load first (longest latency) ---
    const int4* __restrict__ t4 = reinterpret_cast<const int4*>(target)
                                  + (long long)b * n_vec4_per_batch;
    int4 v0 = make_int4(0, 0, 0, 0);
    const bool ld0 = (lane < n_vec4_per_batch);
    if (ld0) v0 = t4[lane];

    // --- overlap: pre-scaled BCE log terms (lanes 0..5) ---
    const int term_idx = b * 6 + lane;
    const bool term_valid = (lane < 6) && (term_idx < n_terms);
    float v_present = 0.0f, v_absent = 0.0f;
    if (term_valid) {
        const float p = se_pred[term_idx];
        v_present = -fmaxf(logf(p),    -100.0f) * inv_n_terms;  // t = 1
        v_absent  = -fmaxf(log1pf(-p), -100.0f) * inv_n_terms;  // t = 0
    }

    // --- presence mask ---
    unsigned acc = 0u;
    if (ld0) {
        acc = (1u << (v0.x & 31)) | (1u << (v0.y & 31)) |
              (1u << (v0.z & 31)) | (1u << (v0.w & 31));
    }
    acc = __reduce_or_sync(0xffffffffu, acc) & 0x3Fu;

    if (acc != 0x3Fu) {                          // cold path: finish the scan
        for (int base = 32; base < n_vec4_per_batch; base += 32) {
            int idx = base + lane;
            unsigned a = 0u;
            if (idx < n_vec4_per_batch) {
                int4 v = t4[idx];
                a = (1u << (v.x & 31)) | (1u << (v.y & 31)) |
                    (1u << (v.z & 31)) | (1u << (v.w & 31));
            }
            acc |= __reduce_or_sync(0xffffffffu, a) & 0x3Fu;
            if (acc == 0x3Fu) break;
        }
    }

    // --- select + reduce this batch's 6 pre-scaled terms ---
    float v = 0.0f;
    if (term_valid)
        v = ((acc >> lane) & 1u) ? v_present : v_absent;
    #pragma unroll
    for (int o = 4; o > 0; o >>= 1) v += __shfl_down_sync(0xffffffffu, v, o);

    if (lane == 0) atomicAdd(out, v);            // return unused -> REDG
}

// ---------------------------------------------------------------------------
extern "C" void kernel_launch(void* const* d_in, const int* in_sizes, int n_in,
                              void* d_out, int out_size) {
    // Resolve inputs by size: se_pred has 64*6 = 384 elements; target is huge.
    int se_idx = 0, tg_idx = 1;
    if (n_in >= 2 && in_sizes[0] > in_sizes[1]) { se_idx = 1; tg_idx = 0; }

    const float* se_pred = (const float*)d_in[se_idx];
    const int*   target  = (const int*)d_in[tg_idx];
    float* out = (float*)d_out;

    const int n_terms   = in_sizes[se_idx];        // 384
    const int B         = n_terms / 6;             // 64
    const int per_batch = in_sizes[tg_idx] / B;    // 262144 int32 labels
    const int n_vec4    = per_batch / 4;           // int4 count per batch
    const int n_blocks  = (B + 3) >> 2;            // 16 CTAs, 4 warps each
    const float inv_n   = 1.0f / (float)n_terms;

    cudaMemsetAsync(out, 0, sizeof(float), 0);     // zero the accumulator
    se_loss_kernel<<<n_blocks, 128>>>(target, se_pred, out,
                                      n_vec4, B, n_terms, inv_n);
}